// round 14
// baseline (speedup 1.0000x reference)
#include <cuda_runtime.h>
#include <math.h>

#define NN 50000
#define CC 256
#define EE 800000
#define HH 64
#define KK 32
#define LL 2
#define NB 64   // nodes per block in tiled node kernels

// ---- scratch (no allocation allowed) ----
__device__ float g_ah[NN * 128];   // per node: [0:64) gate-a proj, [64:128) h
__device__ float g_m[NN * HH];     // scatter accumulator (zero-invariant between replays)
__device__ float g_deg[NN];        // weighted degree (zero-invariant between replays)
__device__ float g_b[NN * HH];     // per-node dst-side gate projection: h @ W1[64:128] + b1
__device__ float g_w0[EE];         // base_w * rho[src] * rho[dst]  (layer-invariant)
__device__ int   g_soff[EE];       // src * 128  (element offset into g_ah)
__device__ int   g_doff[EE];       // dst * 64   (element offset into g_b / g_m)

// 4x4 outer-product FMA tile: acc[n*4+c] += av.n * wv.c
__device__ __forceinline__ void mm16(const float4 av, const float4 wv, float* acc) {
    acc[0]  = fmaf(av.x, wv.x, acc[0]);  acc[1]  = fmaf(av.x, wv.y, acc[1]);
    acc[2]  = fmaf(av.x, wv.z, acc[2]);  acc[3]  = fmaf(av.x, wv.w, acc[3]);
    acc[4]  = fmaf(av.y, wv.x, acc[4]);  acc[5]  = fmaf(av.y, wv.y, acc[5]);
    acc[6]  = fmaf(av.y, wv.z, acc[6]);  acc[7]  = fmaf(av.y, wv.w, acc[7]);
    acc[8]  = fmaf(av.z, wv.x, acc[8]);  acc[9]  = fmaf(av.z, wv.y, acc[9]);
    acc[10] = fmaf(av.z, wv.z, acc[10]); acc[11] = fmaf(av.z, wv.w, acc[11]);
    acc[12] = fmaf(av.w, wv.x, acc[12]); acc[13] = fmaf(av.w, wv.y, acc[13]);
    acc[14] = fmaf(av.w, wv.z, acc[14]); acc[15] = fmaf(av.w, wv.w, acc[15]);
}

__device__ __forceinline__ void zero16(float* acc) {
#pragma unroll
    for (int k = 0; k < 16; k++) acc[k] = 0.f;
}

__device__ __forceinline__ void red_v4(float* addr, float4 v) {
    asm volatile("red.global.add.v4.f32 [%0], {%1, %2, %3, %4};"
                 :: "l"(addr), "f"(v.x), "f"(v.y), "f"(v.z), "f"(v.w) : "memory");
}

// stage a 64x64 row-major global matrix into sW[64][68]
#define STAGE_W(sW, gptr) do {                                            \
    _Pragma("unroll")                                                     \
    for (int _q = 0; _q < 4; _q++) {                                      \
        int _lin = _q * 256 + tid;                                        \
        *(float4*)&sW[_lin >> 4][(_lin & 15) * 4] =                       \
            *(const float4*)&(gptr)[_lin * 4];                            \
    }                                                                     \
} while (0)

// tiled matvec: acc[16] += sA(64 x nodes) x sW(64 x ch) tile at (ng, cg)
#define MATVEC(sA, sW, acc) do {                                          \
    _Pragma("unroll 8")                                                   \
    for (int _i = 0; _i < 64; _i++) {                                     \
        float4 _av = *(float4*)&sA[_i][ng * 4];                           \
        float4 _wv = *(float4*)&sW[_i][cg * 4];                           \
        mm16(_av, _wv, acc);                                              \
    }                                                                     \
} while (0)

// =====================================================================
// Encoder (tiled): h = relu(relu(x @ W1 + b1) @ W2 + b2), then fused
// gate pre-projections a = h@gW1[0:64] -> g_ah[:,0:64],
// h -> g_ah[:,64:128], b = h@gW1[64:128]+gb1 -> g_b.
// =====================================================================
__global__ void __launch_bounds__(256) k_encoder(
        const float* __restrict__ x,
        const float* __restrict__ w1, const float* __restrict__ b1,
        const float* __restrict__ w2, const float* __restrict__ b2,
        const float* __restrict__ gw1, const float* __restrict__ gb1) {
    __shared__ float sA[64][NB + 4];
    __shared__ float sW[64][68];
    int tid = threadIdx.x;
    int cg = tid & 15, ng = tid >> 4;
    int n0 = blockIdx.x * NB;

    float acc[16];
    zero16(acc);

    // ---- layer1: K=256 in 4 chunks of 64 ----
    for (int kb = 0; kb < 4; kb++) {
#pragma unroll
        for (int q = 0; q < 4; q++) {
            int lin = q * 256 + tid;
            int node = lin >> 4;
            int c4 = (lin & 15) * 4;
            int n = n0 + node;
            float4 v = make_float4(0.f, 0.f, 0.f, 0.f);
            if (n < NN) v = *(const float4*)&x[(size_t)n * CC + kb * 64 + c4];
            sA[c4 + 0][node] = v.x; sA[c4 + 1][node] = v.y;
            sA[c4 + 2][node] = v.z; sA[c4 + 3][node] = v.w;
        }
        STAGE_W(sW, w1 + (size_t)kb * 64 * HH);
        __syncthreads();
        MATVEC(sA, sW, acc);
        __syncthreads();
    }

    // h1 = relu(acc + b1); write transposed into sA, stage w2
    {
        float4 bv = *(const float4*)&b1[cg * 4];
        float bb[4] = {bv.x, bv.y, bv.z, bv.w};
#pragma unroll
        for (int n = 0; n < 4; n++)
#pragma unroll
            for (int c = 0; c < 4; c++)
                sA[cg * 4 + c][ng * 4 + n] = fmaxf(acc[n * 4 + c] + bb[c], 0.f);
    }
    STAGE_W(sW, w2);
    __syncthreads();

    zero16(acc);
    MATVEC(sA, sW, acc);
    __syncthreads();

    // h = relu(acc + b2); store to g_ah[:,64:], write transposed into sA
    float hval[16];
    {
        float4 bv = *(const float4*)&b2[cg * 4];
        float bb[4] = {bv.x, bv.y, bv.z, bv.w};
#pragma unroll
        for (int n = 0; n < 4; n++) {
            int node = n0 + ng * 4 + n;
#pragma unroll
            for (int c = 0; c < 4; c++) {
                hval[n * 4 + c] = fmaxf(acc[n * 4 + c] + bb[c], 0.f);
                sA[cg * 4 + c][ng * 4 + n] = hval[n * 4 + c];
            }
            if (node < NN)
                *(float4*)&g_ah[(size_t)node * 128 + 64 + cg * 4] =
                    make_float4(hval[n*4], hval[n*4+1], hval[n*4+2], hval[n*4+3]);
        }
    }
    STAGE_W(sW, gw1);                 // first 64 rows of gate W1
    __syncthreads();

    zero16(acc);
    MATVEC(sA, sW, acc);
#pragma unroll
    for (int n = 0; n < 4; n++) {
        int node = n0 + ng * 4 + n;
        if (node < NN)
            *(float4*)&g_ah[(size_t)node * 128 + cg * 4] =
                make_float4(acc[n*4], acc[n*4+1], acc[n*4+2], acc[n*4+3]);
    }
    __syncthreads();
    STAGE_W(sW, gw1 + (size_t)64 * HH);  // second 64 rows
    __syncthreads();

    zero16(acc);
    MATVEC(sA, sW, acc);
    {
        float4 bv = *(const float4*)&gb1[cg * 4];
        float bb[4] = {bv.x, bv.y, bv.z, bv.w};
#pragma unroll
        for (int n = 0; n < 4; n++) {
            int node = n0 + ng * 4 + n;
            if (node < NN)
                *(float4*)&g_b[(size_t)node * HH + cg * 4] =
                    make_float4(acc[n*4] + bb[0], acc[n*4+1] + bb[1],
                                acc[n*4+2] + bb[2], acc[n*4+3] + bb[3]);
        }
    }
}

// =====================================================================
// w0[e] = base_w * sigmoid(rho_raw[src]) * sigmoid(rho_raw[dst]);
// plus precomputed gather offsets.
// =====================================================================
__global__ void k_w0(const int* __restrict__ src, const int* __restrict__ dst,
                     const float* __restrict__ basew,
                     const float* __restrict__ rho_raw) {
    int i = blockIdx.x * blockDim.x + threadIdx.x;
    if (i < EE) {
        int s = src[i], d = dst[i];
        float rs = 1.f / (1.f + __expf(-rho_raw[s]));
        float rd = 1.f / (1.f + __expf(-rho_raw[d]));
        g_w0[i] = basew[i] * rs * rd;
        g_soff[i] = s * 128;
        g_doff[i] = d * 64;
    }
}

// =====================================================================
// Edge kernel: 8 lanes per edge; lane owns 8 channels (sl*8..sl*8+7).
// A warp carries 4 edges in its lanes simultaneously (q = lane>>3).
// Barrier-free / smem-free.
//   z = relu(a[src] + b[dst]); gate = sigmoid(z @ w2 + b2)
//   wt = w0[e] * gate;  red.v4 x2: m[dst] += wt*h_src ; deg[dst] += wt
// grid = EE/32 exactly.
// =====================================================================
__global__ void __launch_bounds__(256) k_edge(
        const float* __restrict__ gw2, const float* __restrict__ gb2) {
    int tid = threadIdx.x;
    int lane = tid & 31;
    int warp = tid >> 5;
    int q  = lane >> 3;        // edge slot within warp (0..3)
    int sl = lane & 7;         // lane within edge group; channels sl*8..sl*8+7
    int e = (blockIdx.x * 8 + warp) * 4 + q;

    // per-warp weight loads (L1-resident after first blocks)
    float4 w2a = __ldg((const float4*)&gw2[sl * 8]);
    float4 w2b = __ldg((const float4*)&gw2[sl * 8 + 4]);
    float b2v = __ldg(gb2);

    // per-edge metadata: 4 distinct values per warp, broadcast via L1
    int so = __ldg(&g_soff[e]);
    int dofs = __ldg(&g_doff[e]);
    float w0 = __ldg(&g_w0[e]);

    const float* ahp = g_ah + so + sl * 8;
    float4 av0 = *(const float4*)ahp;
    float4 av1 = *(const float4*)(ahp + 4);
    float4 hv0 = *(const float4*)(ahp + 64);
    float4 hv1 = *(const float4*)(ahp + 68);
    const float* bp = g_b + dofs + sl * 8;
    float4 bv0 = *(const float4*)bp;
    float4 bv1 = *(const float4*)(bp + 4);

    float part = fmaxf(av0.x + bv0.x, 0.f) * w2a.x
               + fmaxf(av0.y + bv0.y, 0.f) * w2a.y
               + fmaxf(av0.z + bv0.z, 0.f) * w2a.z
               + fmaxf(av0.w + bv0.w, 0.f) * w2a.w
               + fmaxf(av1.x + bv1.x, 0.f) * w2b.x
               + fmaxf(av1.y + bv1.y, 0.f) * w2b.y
               + fmaxf(av1.z + bv1.z, 0.f) * w2b.z
               + fmaxf(av1.w + bv1.w, 0.f) * w2b.w;

    // butterfly sum over the 8 lanes of this edge (stays inside the group)
    part += __shfl_xor_sync(0xffffffffu, part, 1);
    part += __shfl_xor_sync(0xffffffffu, part, 2);
    part += __shfl_xor_sync(0xffffffffu, part, 4);

    float gate = 1.f / (1.f + __expf(-(part + b2v)));
    float wt = w0 * gate;

    float* mp = g_m + dofs + sl * 8;
    red_v4(mp,     make_float4(wt * hv0.x, wt * hv0.y, wt * hv0.z, wt * hv0.w));
    red_v4(mp + 4, make_float4(wt * hv1.x, wt * hv1.y, wt * hv1.z, wt * hv1.w));
    if (sl == 0) atomicAdd(&g_deg[dofs >> 6], wt);
}

// =====================================================================
// Node update (tiled) + LayerNorm + either next-layer gate projections
// (mode=1) or fused output head (mode=0).
// block = 256 threads, 64 nodes/block. Resets g_m/g_deg (replay invariant).
// =====================================================================
__global__ void __launch_bounds__(256) k_update(
        const float* __restrict__ uw1, const float* __restrict__ ub1,
        const float* __restrict__ uw2, const float* __restrict__ ub2,
        const float* __restrict__ lng, const float* __restrict__ lnb,
        const float* __restrict__ gw1, const float* __restrict__ gb1,
        const float* __restrict__ tw, const float* __restrict__ tb,
        float* __restrict__ out, int mode) {
    __shared__ float sA[64][NB + 4];
    __shared__ float sW[64][68];
    __shared__ float sInv[NB];
    int tid = threadIdx.x;
    int cg = tid & 15, ng = tid >> 4;
    int n0 = blockIdx.x * NB;

    if (tid < NB) {
        int n = n0 + tid;
        float deg = (n < NN) ? g_deg[n] : 0.f;
        sInv[tid] = 1.f / (deg + 1e-8f);
        if (n < NN) g_deg[n] = 0.f;
    }
    __syncthreads();

    // stage neigh = m*inv transposed; reset g_m; stage uw1
#pragma unroll
    for (int q = 0; q < 4; q++) {
        int lin = q * 256 + tid;
        int node = lin >> 4;
        int c4 = (lin & 15) * 4;
        int n = n0 + node;
        float4 v = make_float4(0.f, 0.f, 0.f, 0.f);
        if (n < NN) {
            v = *(const float4*)&g_m[(size_t)n * HH + c4];
            *(float4*)&g_m[(size_t)n * HH + c4] = make_float4(0.f, 0.f, 0.f, 0.f);
        }
        float inv = sInv[node];
        sA[c4 + 0][node] = v.x * inv; sA[c4 + 1][node] = v.y * inv;
        sA[c4 + 2][node] = v.z * inv; sA[c4 + 3][node] = v.w * inv;
    }
    STAGE_W(sW, uw1);
    __syncthreads();

    float acc[16];
    zero16(acc);
    MATVEC(sA, sW, acc);
    __syncthreads();

    // t = relu(acc + ub1) -> transposed into sA; stage uw2
    {
        float4 bv = *(const float4*)&ub1[cg * 4];
        float bb[4] = {bv.x, bv.y, bv.z, bv.w};
#pragma unroll
        for (int n = 0; n < 4; n++)
#pragma unroll
            for (int c = 0; c < 4; c++)
                sA[cg * 4 + c][ng * 4 + n] = fmaxf(acc[n * 4 + c] + bb[c], 0.f);
    }
    STAGE_W(sW, uw2);
    __syncthreads();

    zero16(acc);
    MATVEC(sA, sW, acc);

    // pre = h + u; LayerNorm per node (reduce over 16 cg-threads)
    float pre[16];
    {
        float4 bv = *(const float4*)&ub2[cg * 4];
        float bb[4] = {bv.x, bv.y, bv.z, bv.w};
#pragma unroll
        for (int n = 0; n < 4; n++) {
            int node = n0 + ng * 4 + n;
            float4 h4 = make_float4(0.f, 0.f, 0.f, 0.f);
            if (node < NN)
                h4 = *(const float4*)&g_ah[(size_t)node * 128 + 64 + cg * 4];
            pre[n * 4 + 0] = h4.x + acc[n * 4 + 0] + bb[0];
            pre[n * 4 + 1] = h4.y + acc[n * 4 + 1] + bb[1];
            pre[n * 4 + 2] = h4.z + acc[n * 4 + 2] + bb[2];
            pre[n * 4 + 3] = h4.w + acc[n * 4 + 3] + bb[3];
        }
    }
    float4 gv = *(const float4*)&lng[cg * 4];
    float4 bv = *(const float4*)&lnb[cg * 4];
    float hn[16];
#pragma unroll
    for (int n = 0; n < 4; n++) {
        float s1 = pre[n*4] + pre[n*4+1] + pre[n*4+2] + pre[n*4+3];
        float s2 = pre[n*4]*pre[n*4] + pre[n*4+1]*pre[n*4+1]
                 + pre[n*4+2]*pre[n*4+2] + pre[n*4+3]*pre[n*4+3];
#pragma unroll
        for (int m = 1; m < 16; m <<= 1) {
            s1 += __shfl_xor_sync(0xffffffffu, s1, m);
            s2 += __shfl_xor_sync(0xffffffffu, s2, m);
        }
        float mean = s1 * (1.f / HH);
        float var  = s2 * (1.f / HH) - mean * mean;
        float inv  = rsqrtf(var + 1e-5f);
        hn[n*4+0] = (pre[n*4+0] - mean) * inv * gv.x + bv.x;
        hn[n*4+1] = (pre[n*4+1] - mean) * inv * gv.y + bv.y;
        hn[n*4+2] = (pre[n*4+2] - mean) * inv * gv.z + bv.z;
        hn[n*4+3] = (pre[n*4+3] - mean) * inv * gv.w + bv.w;
    }

    if (mode == 1) {
        // write new h; compute next-layer gate projections a/b
#pragma unroll
        for (int n = 0; n < 4; n++) {
            int node = n0 + ng * 4 + n;
            if (node < NN)
                *(float4*)&g_ah[(size_t)node * 128 + 64 + cg * 4] =
                    make_float4(hn[n*4], hn[n*4+1], hn[n*4+2], hn[n*4+3]);
        }
        __syncthreads();   // all reads of sA/sW done
#pragma unroll
        for (int n = 0; n < 4; n++)
#pragma unroll
            for (int c = 0; c < 4; c++)
                sA[cg * 4 + c][ng * 4 + n] = hn[n * 4 + c];
        STAGE_W(sW, gw1);
        __syncthreads();

        zero16(acc);
        MATVEC(sA, sW, acc);
#pragma unroll
        for (int n = 0; n < 4; n++) {
            int node = n0 + ng * 4 + n;
            if (node < NN)
                *(float4*)&g_ah[(size_t)node * 128 + cg * 4] =
                    make_float4(acc[n*4], acc[n*4+1], acc[n*4+2], acc[n*4+3]);
        }
        __syncthreads();
        STAGE_W(sW, gw1 + (size_t)64 * HH);
        __syncthreads();

        zero16(acc);
        MATVEC(sA, sW, acc);
        float4 gbv = *(const float4*)&gb1[cg * 4];
        float gb[4] = {gbv.x, gbv.y, gbv.z, gbv.w};
#pragma unroll
        for (int n = 0; n < 4; n++) {
            int node = n0 + ng * 4 + n;
            if (node < NN)
                *(float4*)&g_b[(size_t)node * HH + cg * 4] =
                    make_float4(acc[n*4] + gb[0], acc[n*4+1] + gb[1],
                                acc[n*4+2] + gb[2], acc[n*4+3] + gb[3]);
        }
    } else {
        // fused head: U = softplus(h @ toU_w + toU_b)
        __syncthreads();   // all reads of sA/sW done
#pragma unroll
        for (int n = 0; n < 4; n++)
#pragma unroll
            for (int c = 0; c < 4; c++)
                sA[cg * 4 + c][ng * 4 + n] = hn[n * 4 + c];
        // stage toU_w (64 x 32) into sW[:, 0:32]
#pragma unroll
        for (int q = 0; q < 2; q++) {
            int lin = q * 256 + tid;
            int row = lin >> 3, c4 = (lin & 7) * 4;
            *(float4*)&sW[row][c4] = *(const float4*)&tw[row * KK + c4];
        }
        __syncthreads();

        int cg2 = tid & 7, ng2 = tid >> 3;   // 8 col-groups x 32 node-groups
        float a8[8];
#pragma unroll
        for (int k = 0; k < 8; k++) a8[k] = 0.f;
#pragma unroll 8
        for (int i = 0; i < 64; i++) {
            float2 a2 = *(float2*)&sA[i][ng2 * 2];
            float4 w4 = *(float4*)&sW[i][cg2 * 4];
            a8[0] = fmaf(a2.x, w4.x, a8[0]); a8[1] = fmaf(a2.x, w4.y, a8[1]);
            a8[2] = fmaf(a2.x, w4.z, a8[2]); a8[3] = fmaf(a2.x, w4.w, a8[3]);
            a8[4] = fmaf(a2.y, w4.x, a8[4]); a8[5] = fmaf(a2.y, w4.y, a8[5]);
            a8[6] = fmaf(a2.y, w4.z, a8[6]); a8[7] = fmaf(a2.y, w4.w, a8[7]);
        }
        float4 tb4 = *(const float4*)&tb[cg2 * 4];
        float tbb[4] = {tb4.x, tb4.y, tb4.z, tb4.w};
#pragma unroll
        for (int n = 0; n < 2; n++) {
            int node = n0 + ng2 * 2 + n;
            if (node < NN) {
                float4 o;
                float v0 = a8[n*4+0] + tbb[0];
                float v1 = a8[n*4+1] + tbb[1];
                float v2 = a8[n*4+2] + tbb[2];
                float v3 = a8[n*4+3] + tbb[3];
                o.x = log1pf(__expf(-fabsf(v0))) + fmaxf(v0, 0.f);
                o.y = log1pf(__expf(-fabsf(v1))) + fmaxf(v1, 0.f);
                o.z = log1pf(__expf(-fabsf(v2))) + fmaxf(v2, 0.f);
                o.w = log1pf(__expf(-fabsf(v3))) + fmaxf(v3, 0.f);
                *(float4*)&out[(size_t)node * KK + cg2 * 4] = o;
            }
        }
    }
}

// =====================================================================
extern "C" void kernel_launch(void* const* d_in, const int* in_sizes, int n_in,
                              void* d_out, int out_size) {
    const float* x      = (const float*)d_in[0];
    const int*   src    = (const int*)  d_in[1];
    const int*   dst    = (const int*)  d_in[2];
    const float* basew  = (const float*)d_in[3];
    const float* enc_w1 = (const float*)d_in[4];
    const float* enc_b1 = (const float*)d_in[5];
    const float* enc_w2 = (const float*)d_in[6];
    const float* enc_b2 = (const float*)d_in[7];
    const float* gw1    = (const float*)d_in[8];
    const float* gb1    = (const float*)d_in[9];
    const float* gw2    = (const float*)d_in[10];
    const float* gb2    = (const float*)d_in[11];
    const float* uw1    = (const float*)d_in[12];
    const float* ub1    = (const float*)d_in[13];
    const float* uw2    = (const float*)d_in[14];
    const float* ub2    = (const float*)d_in[15];
    const float* lng    = (const float*)d_in[16];
    const float* lnb    = (const float*)d_in[17];
    const float* rho    = (const float*)d_in[18];
    const float* tw     = (const float*)d_in[19];
    const float* tb     = (const float*)d_in[20];
    float* out = (float*)d_out;

    int nblocks = (NN + NB - 1) / NB;
    k_encoder<<<nblocks, 256>>>(x, enc_w1, enc_b1, enc_w2, enc_b2, gw1, gb1);
    k_w0<<<(EE + 255) / 256, 256>>>(src, dst, basew, rho);

    for (int l = 0; l < LL; l++) {
        k_edge<<<EE / 32, 256>>>(gw2, gb2);
        k_update<<<nblocks, 256>>>(uw1 + l * HH * HH, ub1 + l * HH,
                                   uw2 + l * HH * HH, ub2 + l * HH,
                                   lng + l * HH, lnb + l * HH,
                                   gw1, gb1, tw, tb, out,
                                   l < LL - 1 ? 1 : 0);
    }
}

// round 15
// speedup vs baseline: 1.1047x; 1.1047x over previous
#include <cuda_runtime.h>
#include <math.h>

#define NN 50000
#define CC 256
#define EE 800000
#define HH 64
#define KK 32
#define LL 2
#define NB 64   // nodes per block in tiled node kernels

// ---- scratch (no allocation allowed) ----
__device__ float g_ah[NN * 128];   // per node: [0:64) gate-a proj, [64:128) h
__device__ float g_m[NN * HH];     // scatter accumulator (zero-invariant between replays)
__device__ float g_deg[NN];        // weighted degree (zero-invariant between replays)
__device__ float g_b[NN * HH];     // per-node dst-side gate projection: h @ W1[64:128] + b1
__device__ float g_w0[EE];         // base_w * rho[src] * rho[dst]  (layer-invariant)
__device__ int   g_soff[EE];       // src * 128  (element offset into g_ah)
__device__ int   g_doff[EE];       // dst * 64   (element offset into g_b / g_m)

// 4x4 outer-product FMA tile: acc[n*4+c] += av.n * wv.c
__device__ __forceinline__ void mm16(const float4 av, const float4 wv, float* acc) {
    acc[0]  = fmaf(av.x, wv.x, acc[0]);  acc[1]  = fmaf(av.x, wv.y, acc[1]);
    acc[2]  = fmaf(av.x, wv.z, acc[2]);  acc[3]  = fmaf(av.x, wv.w, acc[3]);
    acc[4]  = fmaf(av.y, wv.x, acc[4]);  acc[5]  = fmaf(av.y, wv.y, acc[5]);
    acc[6]  = fmaf(av.y, wv.z, acc[6]);  acc[7]  = fmaf(av.y, wv.w, acc[7]);
    acc[8]  = fmaf(av.z, wv.x, acc[8]);  acc[9]  = fmaf(av.z, wv.y, acc[9]);
    acc[10] = fmaf(av.z, wv.z, acc[10]); acc[11] = fmaf(av.z, wv.w, acc[11]);
    acc[12] = fmaf(av.w, wv.x, acc[12]); acc[13] = fmaf(av.w, wv.y, acc[13]);
    acc[14] = fmaf(av.w, wv.z, acc[14]); acc[15] = fmaf(av.w, wv.w, acc[15]);
}

__device__ __forceinline__ void zero16(float* acc) {
#pragma unroll
    for (int k = 0; k < 16; k++) acc[k] = 0.f;
}

__device__ __forceinline__ void red_v4(float* addr, float4 v) {
    asm volatile("red.global.add.v4.f32 [%0], {%1, %2, %3, %4};"
                 :: "l"(addr), "f"(v.x), "f"(v.y), "f"(v.z), "f"(v.w) : "memory");
}

// stage a 64x64 row-major global matrix into sW[64][68]
#define STAGE_W(sW, gptr) do {                                            \
    _Pragma("unroll")                                                     \
    for (int _q = 0; _q < 4; _q++) {                                      \
        int _lin = _q * 256 + tid;                                        \
        *(float4*)&sW[_lin >> 4][(_lin & 15) * 4] =                       \
            *(const float4*)&(gptr)[_lin * 4];                            \
    }                                                                     \
} while (0)

// tiled matvec: acc[16] += sA(64 x nodes) x sW(64 x ch) tile at (ng, cg)
#define MATVEC(sA, sW, acc) do {                                          \
    _Pragma("unroll 8")                                                   \
    for (int _i = 0; _i < 64; _i++) {                                     \
        float4 _av = *(float4*)&sA[_i][ng * 4];                           \
        float4 _wv = *(float4*)&sW[_i][cg * 4];                           \
        mm16(_av, _wv, acc);                                              \
    }                                                                     \
} while (0)

// =====================================================================
// Encoder (tiled): h = relu(relu(x @ W1 + b1) @ W2 + b2), then fused
// gate pre-projections a = h@gW1[0:64] -> g_ah[:,0:64],
// h -> g_ah[:,64:128], b = h@gW1[64:128]+gb1 -> g_b.
// =====================================================================
__global__ void __launch_bounds__(256) k_encoder(
        const float* __restrict__ x,
        const float* __restrict__ w1, const float* __restrict__ b1,
        const float* __restrict__ w2, const float* __restrict__ b2,
        const float* __restrict__ gw1, const float* __restrict__ gb1) {
    __shared__ float sA[64][NB + 4];
    __shared__ float sW[64][68];
    int tid = threadIdx.x;
    int cg = tid & 15, ng = tid >> 4;
    int n0 = blockIdx.x * NB;

    float acc[16];
    zero16(acc);

    // ---- layer1: K=256 in 4 chunks of 64 ----
    for (int kb = 0; kb < 4; kb++) {
#pragma unroll
        for (int q = 0; q < 4; q++) {
            int lin = q * 256 + tid;
            int node = lin >> 4;
            int c4 = (lin & 15) * 4;
            int n = n0 + node;
            float4 v = make_float4(0.f, 0.f, 0.f, 0.f);
            if (n < NN) v = *(const float4*)&x[(size_t)n * CC + kb * 64 + c4];
            sA[c4 + 0][node] = v.x; sA[c4 + 1][node] = v.y;
            sA[c4 + 2][node] = v.z; sA[c4 + 3][node] = v.w;
        }
        STAGE_W(sW, w1 + (size_t)kb * 64 * HH);
        __syncthreads();
        MATVEC(sA, sW, acc);
        __syncthreads();
    }

    // h1 = relu(acc + b1); write transposed into sA, stage w2
    {
        float4 bv = *(const float4*)&b1[cg * 4];
        float bb[4] = {bv.x, bv.y, bv.z, bv.w};
#pragma unroll
        for (int n = 0; n < 4; n++)
#pragma unroll
            for (int c = 0; c < 4; c++)
                sA[cg * 4 + c][ng * 4 + n] = fmaxf(acc[n * 4 + c] + bb[c], 0.f);
    }
    STAGE_W(sW, w2);
    __syncthreads();

    zero16(acc);
    MATVEC(sA, sW, acc);
    __syncthreads();

    // h = relu(acc + b2); store to g_ah[:,64:], write transposed into sA
    float hval[16];
    {
        float4 bv = *(const float4*)&b2[cg * 4];
        float bb[4] = {bv.x, bv.y, bv.z, bv.w};
#pragma unroll
        for (int n = 0; n < 4; n++) {
            int node = n0 + ng * 4 + n;
#pragma unroll
            for (int c = 0; c < 4; c++) {
                hval[n * 4 + c] = fmaxf(acc[n * 4 + c] + bb[c], 0.f);
                sA[cg * 4 + c][ng * 4 + n] = hval[n * 4 + c];
            }
            if (node < NN)
                *(float4*)&g_ah[(size_t)node * 128 + 64 + cg * 4] =
                    make_float4(hval[n*4], hval[n*4+1], hval[n*4+2], hval[n*4+3]);
        }
    }
    STAGE_W(sW, gw1);                 // first 64 rows of gate W1
    __syncthreads();

    zero16(acc);
    MATVEC(sA, sW, acc);
#pragma unroll
    for (int n = 0; n < 4; n++) {
        int node = n0 + ng * 4 + n;
        if (node < NN)
            *(float4*)&g_ah[(size_t)node * 128 + cg * 4] =
                make_float4(acc[n*4], acc[n*4+1], acc[n*4+2], acc[n*4+3]);
    }
    __syncthreads();
    STAGE_W(sW, gw1 + (size_t)64 * HH);  // second 64 rows
    __syncthreads();

    zero16(acc);
    MATVEC(sA, sW, acc);
    {
        float4 bv = *(const float4*)&gb1[cg * 4];
        float bb[4] = {bv.x, bv.y, bv.z, bv.w};
#pragma unroll
        for (int n = 0; n < 4; n++) {
            int node = n0 + ng * 4 + n;
            if (node < NN)
                *(float4*)&g_b[(size_t)node * HH + cg * 4] =
                    make_float4(acc[n*4] + bb[0], acc[n*4+1] + bb[1],
                                acc[n*4+2] + bb[2], acc[n*4+3] + bb[3]);
        }
    }
}

// =====================================================================
// w0[e] = base_w * sigmoid(rho_raw[src]) * sigmoid(rho_raw[dst]);
// plus precomputed gather offsets.
// =====================================================================
__global__ void k_w0(const int* __restrict__ src, const int* __restrict__ dst,
                     const float* __restrict__ basew,
                     const float* __restrict__ rho_raw) {
    int i = blockIdx.x * blockDim.x + threadIdx.x;
    if (i < EE) {
        int s = src[i], d = dst[i];
        float rs = 1.f / (1.f + __expf(-rho_raw[s]));
        float rd = 1.f / (1.f + __expf(-rho_raw[d]));
        g_w0[i] = basew[i] * rs * rd;
        g_soff[i] = s * 128;
        g_doff[i] = d * 64;
    }
}

// =====================================================================
// Edge kernel: half-warp per edge; lane owns 4 channels.
// Barrier-free / smem-free: w2 and b2 loaded per-warp via __ldg (L1-hot).
// Each warp memory instruction touches only 2 node rows (16 lanes x 16B)
// — keeps wavefronts/instruction minimal (R14 lesson).
//   z = relu(a[src] + b[dst]); gate = sigmoid(z @ w2 + b2)
//   wt = w0[e] * gate;  red.v4: m[dst] += wt*h_src ; deg[dst] += wt
// grid = EE/32 exactly.
// =====================================================================
__global__ void __launch_bounds__(256) k_edge(
        const float* __restrict__ gw2, const float* __restrict__ gb2) {
    int tid = threadIdx.x;
    int lane = tid & 31;
    int warp = tid >> 5;
    int sub = lane >> 4;       // which half-warp
    int sl  = lane & 15;       // lane within half
    int e0 = (blockIdx.x * 8 + warp) * 4;

    // per-warp weight loads (L1-resident after first blocks)
    float4 w2v = __ldg((const float4*)&gw2[sl * 4]);
    float b2v = __ldg(gb2);

    int4 so4 = *(const int4*)&g_soff[e0];
    int4 do4 = *(const int4*)&g_doff[e0];
    float4 w04 = *(const float4*)&g_w0[e0];
    int soE[4] = {so4.x, so4.y, so4.z, so4.w};
    int doE[4] = {do4.x, do4.y, do4.z, do4.w};
    float w0E[4] = {w04.x, w04.y, w04.z, w04.w};

    int doI[2];
    float4 av[2], bv[2], hv[2];
    float w0I[2];
#pragma unroll
    for (int t = 0; t < 2; t++) {
        int ei = t * 2 + sub;
        doI[t] = doE[ei]; w0I[t] = w0E[ei];
        const float* ahp = g_ah + soE[ei] + sl * 4;
        av[t] = *(const float4*)ahp;
        hv[t] = *(const float4*)(ahp + 64);
        bv[t] = *(const float4*)(g_b + doI[t] + sl * 4);
    }

    float part[2];
#pragma unroll
    for (int t = 0; t < 2; t++)
        part[t] = fmaxf(av[t].x + bv[t].x, 0.f) * w2v.x
                + fmaxf(av[t].y + bv[t].y, 0.f) * w2v.y
                + fmaxf(av[t].z + bv[t].z, 0.f) * w2v.z
                + fmaxf(av[t].w + bv[t].w, 0.f) * w2v.w;

#pragma unroll
    for (int off = 8; off; off >>= 1) {
        part[0] += __shfl_xor_sync(0xffffffffu, part[0], off);
        part[1] += __shfl_xor_sync(0xffffffffu, part[1], off);
    }

#pragma unroll
    for (int t = 0; t < 2; t++) {
        float gate = 1.f / (1.f + __expf(-(part[t] + b2v)));
        float wt = w0I[t] * gate;
        float4 mv = make_float4(wt * hv[t].x, wt * hv[t].y,
                                wt * hv[t].z, wt * hv[t].w);
        red_v4(&g_m[doI[t] + sl * 4], mv);
        if (sl == 0) atomicAdd(&g_deg[doI[t] >> 6], wt);
    }
}

// =====================================================================
// Node update (tiled) + LayerNorm + either next-layer gate projections
// (mode=1) or fused output head (mode=0).
// block = 256 threads, 64 nodes/block. Resets g_m/g_deg (replay invariant).
// =====================================================================
__global__ void __launch_bounds__(256) k_update(
        const float* __restrict__ uw1, const float* __restrict__ ub1,
        const float* __restrict__ uw2, const float* __restrict__ ub2,
        const float* __restrict__ lng, const float* __restrict__ lnb,
        const float* __restrict__ gw1, const float* __restrict__ gb1,
        const float* __restrict__ tw, const float* __restrict__ tb,
        float* __restrict__ out, int mode) {
    __shared__ float sA[64][NB + 4];
    __shared__ float sW[64][68];
    __shared__ float sInv[NB];
    int tid = threadIdx.x;
    int cg = tid & 15, ng = tid >> 4;
    int n0 = blockIdx.x * NB;

    if (tid < NB) {
        int n = n0 + tid;
        float deg = (n < NN) ? g_deg[n] : 0.f;
        sInv[tid] = 1.f / (deg + 1e-8f);
        if (n < NN) g_deg[n] = 0.f;
    }
    __syncthreads();

    // stage neigh = m*inv transposed; reset g_m; stage uw1
#pragma unroll
    for (int q = 0; q < 4; q++) {
        int lin = q * 256 + tid;
        int node = lin >> 4;
        int c4 = (lin & 15) * 4;
        int n = n0 + node;
        float4 v = make_float4(0.f, 0.f, 0.f, 0.f);
        if (n < NN) {
            v = *(const float4*)&g_m[(size_t)n * HH + c4];
            *(float4*)&g_m[(size_t)n * HH + c4] = make_float4(0.f, 0.f, 0.f, 0.f);
        }
        float inv = sInv[node];
        sA[c4 + 0][node] = v.x * inv; sA[c4 + 1][node] = v.y * inv;
        sA[c4 + 2][node] = v.z * inv; sA[c4 + 3][node] = v.w * inv;
    }
    STAGE_W(sW, uw1);
    __syncthreads();

    float acc[16];
    zero16(acc);
    MATVEC(sA, sW, acc);
    __syncthreads();

    // t = relu(acc + ub1) -> transposed into sA; stage uw2
    {
        float4 bv = *(const float4*)&ub1[cg * 4];
        float bb[4] = {bv.x, bv.y, bv.z, bv.w};
#pragma unroll
        for (int n = 0; n < 4; n++)
#pragma unroll
            for (int c = 0; c < 4; c++)
                sA[cg * 4 + c][ng * 4 + n] = fmaxf(acc[n * 4 + c] + bb[c], 0.f);
    }
    STAGE_W(sW, uw2);
    __syncthreads();

    zero16(acc);
    MATVEC(sA, sW, acc);

    // pre = h + u; LayerNorm per node (reduce over 16 cg-threads)
    float pre[16];
    {
        float4 bv = *(const float4*)&ub2[cg * 4];
        float bb[4] = {bv.x, bv.y, bv.z, bv.w};
#pragma unroll
        for (int n = 0; n < 4; n++) {
            int node = n0 + ng * 4 + n;
            float4 h4 = make_float4(0.f, 0.f, 0.f, 0.f);
            if (node < NN)
                h4 = *(const float4*)&g_ah[(size_t)node * 128 + 64 + cg * 4];
            pre[n * 4 + 0] = h4.x + acc[n * 4 + 0] + bb[0];
            pre[n * 4 + 1] = h4.y + acc[n * 4 + 1] + bb[1];
            pre[n * 4 + 2] = h4.z + acc[n * 4 + 2] + bb[2];
            pre[n * 4 + 3] = h4.w + acc[n * 4 + 3] + bb[3];
        }
    }
    float4 gv = *(const float4*)&lng[cg * 4];
    float4 bv = *(const float4*)&lnb[cg * 4];
    float hn[16];
#pragma unroll
    for (int n = 0; n < 4; n++) {
        float s1 = pre[n*4] + pre[n*4+1] + pre[n*4+2] + pre[n*4+3];
        float s2 = pre[n*4]*pre[n*4] + pre[n*4+1]*pre[n*4+1]
                 + pre[n*4+2]*pre[n*4+2] + pre[n*4+3]*pre[n*4+3];
#pragma unroll
        for (int m = 1; m < 16; m <<= 1) {
            s1 += __shfl_xor_sync(0xffffffffu, s1, m);
            s2 += __shfl_xor_sync(0xffffffffu, s2, m);
        }
        float mean = s1 * (1.f / HH);
        float var  = s2 * (1.f / HH) - mean * mean;
        float inv  = rsqrtf(var + 1e-5f);
        hn[n*4+0] = (pre[n*4+0] - mean) * inv * gv.x + bv.x;
        hn[n*4+1] = (pre[n*4+1] - mean) * inv * gv.y + bv.y;
        hn[n*4+2] = (pre[n*4+2] - mean) * inv * gv.z + bv.z;
        hn[n*4+3] = (pre[n*4+3] - mean) * inv * gv.w + bv.w;
    }

    if (mode == 1) {
        // write new h; compute next-layer gate projections a/b
#pragma unroll
        for (int n = 0; n < 4; n++) {
            int node = n0 + ng * 4 + n;
            if (node < NN)
                *(float4*)&g_ah[(size_t)node * 128 + 64 + cg * 4] =
                    make_float4(hn[n*4], hn[n*4+1], hn[n*4+2], hn[n*4+3]);
        }
        __syncthreads();   // all reads of sA/sW done
#pragma unroll
        for (int n = 0; n < 4; n++)
#pragma unroll
            for (int c = 0; c < 4; c++)
                sA[cg * 4 + c][ng * 4 + n] = hn[n * 4 + c];
        STAGE_W(sW, gw1);
        __syncthreads();

        zero16(acc);
        MATVEC(sA, sW, acc);
#pragma unroll
        for (int n = 0; n < 4; n++) {
            int node = n0 + ng * 4 + n;
            if (node < NN)
                *(float4*)&g_ah[(size_t)node * 128 + cg * 4] =
                    make_float4(acc[n*4], acc[n*4+1], acc[n*4+2], acc[n*4+3]);
        }
        __syncthreads();
        STAGE_W(sW, gw1 + (size_t)64 * HH);
        __syncthreads();

        zero16(acc);
        MATVEC(sA, sW, acc);
        float4 gbv = *(const float4*)&gb1[cg * 4];
        float gb[4] = {gbv.x, gbv.y, gbv.z, gbv.w};
#pragma unroll
        for (int n = 0; n < 4; n++) {
            int node = n0 + ng * 4 + n;
            if (node < NN)
                *(float4*)&g_b[(size_t)node * HH + cg * 4] =
                    make_float4(acc[n*4] + gb[0], acc[n*4+1] + gb[1],
                                acc[n*4+2] + gb[2], acc[n*4+3] + gb[3]);
        }
    } else {
        // fused head: U = softplus(h @ toU_w + toU_b)
        __syncthreads();   // all reads of sA/sW done
#pragma unroll
        for (int n = 0; n < 4; n++)
#pragma unroll
            for (int c = 0; c < 4; c++)
                sA[cg * 4 + c][ng * 4 + n] = hn[n * 4 + c];
        // stage toU_w (64 x 32) into sW[:, 0:32]
#pragma unroll
        for (int q = 0; q < 2; q++) {
            int lin = q * 256 + tid;
            int row = lin >> 3, c4 = (lin & 7) * 4;
            *(float4*)&sW[row][c4] = *(const float4*)&tw[row * KK + c4];
        }
        __syncthreads();

        int cg2 = tid & 7, ng2 = tid >> 3;   // 8 col-groups x 32 node-groups
        float a8[8];
#pragma unroll
        for (int k = 0; k < 8; k++) a8[k] = 0.f;
#pragma unroll 8
        for (int i = 0; i < 64; i++) {
            float2 a2 = *(float2*)&sA[i][ng2 * 2];
            float4 w4 = *(float4*)&sW[i][cg2 * 4];
            a8[0] = fmaf(a2.x, w4.x, a8[0]); a8[1] = fmaf(a2.x, w4.y, a8[1]);
            a8[2] = fmaf(a2.x, w4.z, a8[2]); a8[3] = fmaf(a2.x, w4.w, a8[3]);
            a8[4] = fmaf(a2.y, w4.x, a8[4]); a8[5] = fmaf(a2.y, w4.y, a8[5]);
            a8[6] = fmaf(a2.y, w4.z, a8[6]); a8[7] = fmaf(a2.y, w4.w, a8[7]);
        }
        float4 tb4 = *(const float4*)&tb[cg2 * 4];
        float tbb[4] = {tb4.x, tb4.y, tb4.z, tb4.w};
#pragma unroll
        for (int n = 0; n < 2; n++) {
            int node = n0 + ng2 * 2 + n;
            if (node < NN) {
                float4 o;
                float v0 = a8[n*4+0] + tbb[0];
                float v1 = a8[n*4+1] + tbb[1];
                float v2 = a8[n*4+2] + tbb[2];
                float v3 = a8[n*4+3] + tbb[3];
                o.x = log1pf(__expf(-fabsf(v0))) + fmaxf(v0, 0.f);
                o.y = log1pf(__expf(-fabsf(v1))) + fmaxf(v1, 0.f);
                o.z = log1pf(__expf(-fabsf(v2))) + fmaxf(v2, 0.f);
                o.w = log1pf(__expf(-fabsf(v3))) + fmaxf(v3, 0.f);
                *(float4*)&out[(size_t)node * KK + cg2 * 4] = o;
            }
        }
    }
}

// =====================================================================
extern "C" void kernel_launch(void* const* d_in, const int* in_sizes, int n_in,
                              void* d_out, int out_size) {
    const float* x      = (const float*)d_in[0];
    const int*   src    = (const int*)  d_in[1];
    const int*   dst    = (const int*)  d_in[2];
    const float* basew  = (const float*)d_in[3];
    const float* enc_w1 = (const float*)d_in[4];
    const float* enc_b1 = (const float*)d_in[5];
    const float* enc_w2 = (const float*)d_in[6];
    const float* enc_b2 = (const float*)d_in[7];
    const float* gw1    = (const float*)d_in[8];
    const float* gb1    = (const float*)d_in[9];
    const float* gw2    = (const float*)d_in[10];
    const float* gb2    = (const float*)d_in[11];
    const float* uw1    = (const float*)d_in[12];
    const float* ub1    = (const float*)d_in[13];
    const float* uw2    = (const float*)d_in[14];
    const float* ub2    = (const float*)d_in[15];
    const float* lng    = (const float*)d_in[16];
    const float* lnb    = (const float*)d_in[17];
    const float* rho    = (const float*)d_in[18];
    const float* tw     = (const float*)d_in[19];
    const float* tb     = (const float*)d_in[20];
    float* out = (float*)d_out;

    int nblocks = (NN + NB - 1) / NB;
    k_encoder<<<nblocks, 256>>>(x, enc_w1, enc_b1, enc_w2, enc_b2, gw1, gb1);
    k_w0<<<(EE + 255) / 256, 256>>>(src, dst, basew, rho);

    for (int l = 0; l < LL; l++) {
        k_edge<<<EE / 32, 256>>>(gw2, gb2);
        k_update<<<nblocks, 256>>>(uw1 + l * HH * HH, ub1 + l * HH,
                                   uw2 + l * HH * HH, ub2 + l * HH,
                                   lng + l * HH, lnb + l * HH,
                                   gw1, gb1, tw, tb, out,
                                   l < LL - 1 ? 1 : 0);
    }
}

// round 16
// speedup vs baseline: 1.1216x; 1.0153x over previous
#include <cuda_runtime.h>
#include <math.h>

#define NN 50000
#define CC 256
#define EE 800000
#define HH 64
#define KK 32
#define LL 2
#define NB 64   // nodes per block in tiled node kernels

// ---- scratch (no allocation allowed) ----
__device__ float g_ah[NN * 128];   // per node: [0:64) gate-a proj, [64:128) h
__device__ float g_m[NN * HH];     // scatter accumulator (zero-invariant between replays)
__device__ float g_deg[NN];        // weighted degree (zero-invariant between replays)
__device__ float g_b[NN * HH];     // per-node dst-side gate projection: h @ W1[64:128] + b1
__device__ float g_w0[EE];         // base_w * rho[src] * rho[dst]  (layer-invariant)
__device__ int   g_soff[EE];       // src * 128  (element offset into g_ah)
__device__ int   g_doff[EE];       // dst * 64   (element offset into g_b / g_m)

// dynamic smem for k_update: sA[64][68] | sW0[64][68] | sW1[64][68] | sInv[64]
#define TILE_FLOATS (64 * 68)
#define DSM_FLOATS  (3 * TILE_FLOATS + 64)
#define DSM_BYTES   (DSM_FLOATS * 4)

// 4x4 outer-product FMA tile: acc[n*4+c] += av.n * wv.c
__device__ __forceinline__ void mm16(const float4 av, const float4 wv, float* acc) {
    acc[0]  = fmaf(av.x, wv.x, acc[0]);  acc[1]  = fmaf(av.x, wv.y, acc[1]);
    acc[2]  = fmaf(av.x, wv.z, acc[2]);  acc[3]  = fmaf(av.x, wv.w, acc[3]);
    acc[4]  = fmaf(av.y, wv.x, acc[4]);  acc[5]  = fmaf(av.y, wv.y, acc[5]);
    acc[6]  = fmaf(av.y, wv.z, acc[6]);  acc[7]  = fmaf(av.y, wv.w, acc[7]);
    acc[8]  = fmaf(av.z, wv.x, acc[8]);  acc[9]  = fmaf(av.z, wv.y, acc[9]);
    acc[10] = fmaf(av.z, wv.z, acc[10]); acc[11] = fmaf(av.z, wv.w, acc[11]);
    acc[12] = fmaf(av.w, wv.x, acc[12]); acc[13] = fmaf(av.w, wv.y, acc[13]);
    acc[14] = fmaf(av.w, wv.z, acc[14]); acc[15] = fmaf(av.w, wv.w, acc[15]);
}

__device__ __forceinline__ void zero16(float* acc) {
#pragma unroll
    for (int k = 0; k < 16; k++) acc[k] = 0.f;
}

__device__ __forceinline__ void red_v4(float* addr, float4 v) {
    asm volatile("red.global.add.v4.f32 [%0], {%1, %2, %3, %4};"
                 :: "l"(addr), "f"(v.x), "f"(v.y), "f"(v.z), "f"(v.w) : "memory");
}

// stage a 64x64 row-major global matrix into sW[64][68]
#define STAGE_W(sW, gptr) do {                                            \
    _Pragma("unroll")                                                     \
    for (int _q = 0; _q < 4; _q++) {                                      \
        int _lin = _q * 256 + tid;                                        \
        *(float4*)&sW[_lin >> 4][(_lin & 15) * 4] =                       \
            *(const float4*)&(gptr)[_lin * 4];                            \
    }                                                                     \
} while (0)

// tiled matvec: acc[16] += sA(64 x nodes) x sW(64 x ch) tile at (ng, cg)
#define MATVEC(sA, sW, acc) do {                                          \
    _Pragma("unroll 8")                                                   \
    for (int _i = 0; _i < 64; _i++) {                                     \
        float4 _av = *(float4*)&sA[_i][ng * 4];                           \
        float4 _wv = *(float4*)&sW[_i][cg * 4];                           \
        mm16(_av, _wv, acc);                                              \
    }                                                                     \
} while (0)

// =====================================================================
// Encoder (tiled): unchanged from R12/R15 best.
// =====================================================================
__global__ void __launch_bounds__(256) k_encoder(
        const float* __restrict__ x,
        const float* __restrict__ w1, const float* __restrict__ b1,
        const float* __restrict__ w2, const float* __restrict__ b2,
        const float* __restrict__ gw1, const float* __restrict__ gb1) {
    __shared__ float sA[64][NB + 4];
    __shared__ float sW[64][68];
    int tid = threadIdx.x;
    int cg = tid & 15, ng = tid >> 4;
    int n0 = blockIdx.x * NB;

    float acc[16];
    zero16(acc);

    for (int kb = 0; kb < 4; kb++) {
#pragma unroll
        for (int q = 0; q < 4; q++) {
            int lin = q * 256 + tid;
            int node = lin >> 4;
            int c4 = (lin & 15) * 4;
            int n = n0 + node;
            float4 v = make_float4(0.f, 0.f, 0.f, 0.f);
            if (n < NN) v = *(const float4*)&x[(size_t)n * CC + kb * 64 + c4];
            sA[c4 + 0][node] = v.x; sA[c4 + 1][node] = v.y;
            sA[c4 + 2][node] = v.z; sA[c4 + 3][node] = v.w;
        }
        STAGE_W(sW, w1 + (size_t)kb * 64 * HH);
        __syncthreads();
        MATVEC(sA, sW, acc);
        __syncthreads();
    }

    {
        float4 bv = *(const float4*)&b1[cg * 4];
        float bb[4] = {bv.x, bv.y, bv.z, bv.w};
#pragma unroll
        for (int n = 0; n < 4; n++)
#pragma unroll
            for (int c = 0; c < 4; c++)
                sA[cg * 4 + c][ng * 4 + n] = fmaxf(acc[n * 4 + c] + bb[c], 0.f);
    }
    STAGE_W(sW, w2);
    __syncthreads();

    zero16(acc);
    MATVEC(sA, sW, acc);
    __syncthreads();

    float hval[16];
    {
        float4 bv = *(const float4*)&b2[cg * 4];
        float bb[4] = {bv.x, bv.y, bv.z, bv.w};
#pragma unroll
        for (int n = 0; n < 4; n++) {
            int node = n0 + ng * 4 + n;
#pragma unroll
            for (int c = 0; c < 4; c++) {
                hval[n * 4 + c] = fmaxf(acc[n * 4 + c] + bb[c], 0.f);
                sA[cg * 4 + c][ng * 4 + n] = hval[n * 4 + c];
            }
            if (node < NN)
                *(float4*)&g_ah[(size_t)node * 128 + 64 + cg * 4] =
                    make_float4(hval[n*4], hval[n*4+1], hval[n*4+2], hval[n*4+3]);
        }
    }
    STAGE_W(sW, gw1);
    __syncthreads();

    zero16(acc);
    MATVEC(sA, sW, acc);
#pragma unroll
    for (int n = 0; n < 4; n++) {
        int node = n0 + ng * 4 + n;
        if (node < NN)
            *(float4*)&g_ah[(size_t)node * 128 + cg * 4] =
                make_float4(acc[n*4], acc[n*4+1], acc[n*4+2], acc[n*4+3]);
    }
    __syncthreads();
    STAGE_W(sW, gw1 + (size_t)64 * HH);
    __syncthreads();

    zero16(acc);
    MATVEC(sA, sW, acc);
    {
        float4 bv = *(const float4*)&gb1[cg * 4];
        float bb[4] = {bv.x, bv.y, bv.z, bv.w};
#pragma unroll
        for (int n = 0; n < 4; n++) {
            int node = n0 + ng * 4 + n;
            if (node < NN)
                *(float4*)&g_b[(size_t)node * HH + cg * 4] =
                    make_float4(acc[n*4] + bb[0], acc[n*4+1] + bb[1],
                                acc[n*4+2] + bb[2], acc[n*4+3] + bb[3]);
        }
    }
}

// =====================================================================
__global__ void k_w0(const int* __restrict__ src, const int* __restrict__ dst,
                     const float* __restrict__ basew,
                     const float* __restrict__ rho_raw) {
    int i = blockIdx.x * blockDim.x + threadIdx.x;
    if (i < EE) {
        int s = src[i], d = dst[i];
        float rs = 1.f / (1.f + __expf(-rho_raw[s]));
        float rd = 1.f / (1.f + __expf(-rho_raw[d]));
        g_w0[i] = basew[i] * rs * rd;
        g_soff[i] = s * 128;
        g_doff[i] = d * 64;
    }
}

// =====================================================================
// Edge kernel: half-warp per edge (R12/R15 best formulation, unchanged).
// =====================================================================
__global__ void __launch_bounds__(256) k_edge(
        const float* __restrict__ gw2, const float* __restrict__ gb2) {
    int tid = threadIdx.x;
    int lane = tid & 31;
    int warp = tid >> 5;
    int sub = lane >> 4;
    int sl  = lane & 15;
    int e0 = (blockIdx.x * 8 + warp) * 4;

    float4 w2v = __ldg((const float4*)&gw2[sl * 4]);
    float b2v = __ldg(gb2);

    int4 so4 = *(const int4*)&g_soff[e0];
    int4 do4 = *(const int4*)&g_doff[e0];
    float4 w04 = *(const float4*)&g_w0[e0];
    int soE[4] = {so4.x, so4.y, so4.z, so4.w};
    int doE[4] = {do4.x, do4.y, do4.z, do4.w};
    float w0E[4] = {w04.x, w04.y, w04.z, w04.w};

    int doI[2];
    float4 av[2], bv[2], hv[2];
    float w0I[2];
#pragma unroll
    for (int t = 0; t < 2; t++) {
        int ei = t * 2 + sub;
        doI[t] = doE[ei]; w0I[t] = w0E[ei];
        const float* ahp = g_ah + soE[ei] + sl * 4;
        av[t] = *(const float4*)ahp;
        hv[t] = *(const float4*)(ahp + 64);
        bv[t] = *(const float4*)(g_b + doI[t] + sl * 4);
    }

    float part[2];
#pragma unroll
    for (int t = 0; t < 2; t++)
        part[t] = fmaxf(av[t].x + bv[t].x, 0.f) * w2v.x
                + fmaxf(av[t].y + bv[t].y, 0.f) * w2v.y
                + fmaxf(av[t].z + bv[t].z, 0.f) * w2v.z
                + fmaxf(av[t].w + bv[t].w, 0.f) * w2v.w;

#pragma unroll
    for (int off = 8; off; off >>= 1) {
        part[0] += __shfl_xor_sync(0xffffffffu, part[0], off);
        part[1] += __shfl_xor_sync(0xffffffffu, part[1], off);
    }

#pragma unroll
    for (int t = 0; t < 2; t++) {
        float gate = 1.f / (1.f + __expf(-(part[t] + b2v)));
        float wt = w0I[t] * gate;
        float4 mv = make_float4(wt * hv[t].x, wt * hv[t].y,
                                wt * hv[t].z, wt * hv[t].w);
        red_v4(&g_m[doI[t] + sl * 4], mv);
        if (sl == 0) atomicAdd(&g_deg[doI[t] >> 6], wt);
    }
}

// =====================================================================
// Node update (tiled, double-buffered weight staging) + LayerNorm +
// gate projections (mode=1) or fused head (mode=0).
// Weight stages prefetch into the idle buffer so their LDG latency hides
// under the preceding matvec; the two gate matvecs run barrier-free.
// Resets g_m/g_deg (replay invariant).
// =====================================================================
__global__ void __launch_bounds__(256) k_update(
        const float* __restrict__ uw1, const float* __restrict__ ub1,
        const float* __restrict__ uw2, const float* __restrict__ ub2,
        const float* __restrict__ lng, const float* __restrict__ lnb,
        const float* __restrict__ gw1, const float* __restrict__ gb1,
        const float* __restrict__ tw, const float* __restrict__ tb,
        float* __restrict__ out, int mode) {
    extern __shared__ float dsm[];
    float (*sA)[68]  = (float(*)[68])dsm;
    float (*sW0)[68] = (float(*)[68])(dsm + TILE_FLOATS);
    float (*sW1)[68] = (float(*)[68])(dsm + 2 * TILE_FLOATS);
    float *sInv      = dsm + 3 * TILE_FLOATS;
    int tid = threadIdx.x;
    int cg = tid & 15, ng = tid >> 4;
    int n0 = blockIdx.x * NB;

    if (tid < NB) {
        int n = n0 + tid;
        float deg = (n < NN) ? g_deg[n] : 0.f;
        sInv[tid] = 1.f / (deg + 1e-8f);
        if (n < NN) g_deg[n] = 0.f;
    }
    __syncthreads();

    // stage neigh = m*inv transposed; reset g_m; stage uw1 into sW0
#pragma unroll
    for (int q = 0; q < 4; q++) {
        int lin = q * 256 + tid;
        int node = lin >> 4;
        int c4 = (lin & 15) * 4;
        int n = n0 + node;
        float4 v = make_float4(0.f, 0.f, 0.f, 0.f);
        if (n < NN) {
            v = *(const float4*)&g_m[(size_t)n * HH + c4];
            *(float4*)&g_m[(size_t)n * HH + c4] = make_float4(0.f, 0.f, 0.f, 0.f);
        }
        float inv = sInv[node];
        sA[c4 + 0][node] = v.x * inv; sA[c4 + 1][node] = v.y * inv;
        sA[c4 + 2][node] = v.z * inv; sA[c4 + 3][node] = v.w * inv;
    }
    STAGE_W(sW0, uw1);
    __syncthreads();

    // prefetch uw2 into sW1 (hidden under matvec on sW0)
    STAGE_W(sW1, uw2);

    float acc[16];
    zero16(acc);
    MATVEC(sA, sW0, acc);
    __syncthreads();          // sA readers done; sW1 staged

    // t = relu(acc + ub1) -> transposed into sA
    {
        float4 bv = *(const float4*)&ub1[cg * 4];
        float bb[4] = {bv.x, bv.y, bv.z, bv.w};
#pragma unroll
        for (int n = 0; n < 4; n++)
#pragma unroll
            for (int c = 0; c < 4; c++)
                sA[cg * 4 + c][ng * 4 + n] = fmaxf(acc[n * 4 + c] + bb[c], 0.f);
    }
    // prefetch next weights into sW0 (hidden under matvec on sW1)
    if (mode == 1) {
        STAGE_W(sW0, gw1);
    } else {
        // stage toU_w (64 x 32) into sW0[:, 0:32]
#pragma unroll
        for (int q = 0; q < 2; q++) {
            int lin = q * 256 + tid;
            int row = lin >> 3, c4 = (lin & 7) * 4;
            *(float4*)&sW0[row][c4] = *(const float4*)&tw[row * KK + c4];
        }
    }
    __syncthreads();

    zero16(acc);
    MATVEC(sA, sW1, acc);

    // pre = h + u; LayerNorm per node
    float pre[16];
    {
        float4 bv = *(const float4*)&ub2[cg * 4];
        float bb[4] = {bv.x, bv.y, bv.z, bv.w};
#pragma unroll
        for (int n = 0; n < 4; n++) {
            int node = n0 + ng * 4 + n;
            float4 h4 = make_float4(0.f, 0.f, 0.f, 0.f);
            if (node < NN)
                h4 = *(const float4*)&g_ah[(size_t)node * 128 + 64 + cg * 4];
            pre[n * 4 + 0] = h4.x + acc[n * 4 + 0] + bb[0];
            pre[n * 4 + 1] = h4.y + acc[n * 4 + 1] + bb[1];
            pre[n * 4 + 2] = h4.z + acc[n * 4 + 2] + bb[2];
            pre[n * 4 + 3] = h4.w + acc[n * 4 + 3] + bb[3];
        }
    }
    float4 gv = *(const float4*)&lng[cg * 4];
    float4 bv = *(const float4*)&lnb[cg * 4];
    float hn[16];
#pragma unroll
    for (int n = 0; n < 4; n++) {
        float s1 = pre[n*4] + pre[n*4+1] + pre[n*4+2] + pre[n*4+3];
        float s2 = pre[n*4]*pre[n*4] + pre[n*4+1]*pre[n*4+1]
                 + pre[n*4+2]*pre[n*4+2] + pre[n*4+3]*pre[n*4+3];
#pragma unroll
        for (int m = 1; m < 16; m <<= 1) {
            s1 += __shfl_xor_sync(0xffffffffu, s1, m);
            s2 += __shfl_xor_sync(0xffffffffu, s2, m);
        }
        float mean = s1 * (1.f / HH);
        float var  = s2 * (1.f / HH) - mean * mean;
        float inv  = rsqrtf(var + 1e-5f);
        hn[n*4+0] = (pre[n*4+0] - mean) * inv * gv.x + bv.x;
        hn[n*4+1] = (pre[n*4+1] - mean) * inv * gv.y + bv.y;
        hn[n*4+2] = (pre[n*4+2] - mean) * inv * gv.z + bv.z;
        hn[n*4+3] = (pre[n*4+3] - mean) * inv * gv.w + bv.w;
    }

    if (mode == 1) {
        // write new h
#pragma unroll
        for (int n = 0; n < 4; n++) {
            int node = n0 + ng * 4 + n;
            if (node < NN)
                *(float4*)&g_ah[(size_t)node * 128 + 64 + cg * 4] =
                    make_float4(hn[n*4], hn[n*4+1], hn[n*4+2], hn[n*4+3]);
        }
        __syncthreads();   // sA readers (matvec on sW1) done
#pragma unroll
        for (int n = 0; n < 4; n++)
#pragma unroll
            for (int c = 0; c < 4; c++)
                sA[cg * 4 + c][ng * 4 + n] = hn[n * 4 + c];
        STAGE_W(sW1, gw1 + (size_t)64 * HH);   // prefetch second gate half
        __syncthreads();

        // gate matvecs back-to-back: sA fixed, both weight tiles staged
        zero16(acc);
        MATVEC(sA, sW0, acc);
#pragma unroll
        for (int n = 0; n < 4; n++) {
            int node = n0 + ng * 4 + n;
            if (node < NN)
                *(float4*)&g_ah[(size_t)node * 128 + cg * 4] =
                    make_float4(acc[n*4], acc[n*4+1], acc[n*4+2], acc[n*4+3]);
        }

        zero16(acc);
        MATVEC(sA, sW1, acc);
        float4 gbv = *(const float4*)&gb1[cg * 4];
        float gb[4] = {gbv.x, gbv.y, gbv.z, gbv.w};
#pragma unroll
        for (int n = 0; n < 4; n++) {
            int node = n0 + ng * 4 + n;
            if (node < NN)
                *(float4*)&g_b[(size_t)node * HH + cg * 4] =
                    make_float4(acc[n*4] + gb[0], acc[n*4+1] + gb[1],
                                acc[n*4+2] + gb[2], acc[n*4+3] + gb[3]);
        }
    } else {
        // fused head: U = softplus(h @ toU_w + toU_b); tw already in sW0
        __syncthreads();
#pragma unroll
        for (int n = 0; n < 4; n++)
#pragma unroll
            for (int c = 0; c < 4; c++)
                sA[cg * 4 + c][ng * 4 + n] = hn[n * 4 + c];
        __syncthreads();

        int cg2 = tid & 7, ng2 = tid >> 3;   // 8 col-groups x 32 node-groups
        float a8[8];
#pragma unroll
        for (int k = 0; k < 8; k++) a8[k] = 0.f;
#pragma unroll 8
        for (int i = 0; i < 64; i++) {
            float2 a2 = *(float2*)&sA[i][ng2 * 2];
            float4 w4 = *(float4*)&sW0[i][cg2 * 4];
            a8[0] = fmaf(a2.x, w4.x, a8[0]); a8[1] = fmaf(a2.x, w4.y, a8[1]);
            a8[2] = fmaf(a2.x, w4.z, a8[2]); a8[3] = fmaf(a2.x, w4.w, a8[3]);
            a8[4] = fmaf(a2.y, w4.x, a8[4]); a8[5] = fmaf(a2.y, w4.y, a8[5]);
            a8[6] = fmaf(a2.y, w4.z, a8[6]); a8[7] = fmaf(a2.y, w4.w, a8[7]);
        }
        float4 tb4 = *(const float4*)&tb[cg2 * 4];
        float tbb[4] = {tb4.x, tb4.y, tb4.z, tb4.w};
#pragma unroll
        for (int n = 0; n < 2; n++) {
            int node = n0 + ng2 * 2 + n;
            if (node < NN) {
                float4 o;
                float v0 = a8[n*4+0] + tbb[0];
                float v1 = a8[n*4+1] + tbb[1];
                float v2 = a8[n*4+2] + tbb[2];
                float v3 = a8[n*4+3] + tbb[3];
                o.x = log1pf(__expf(-fabsf(v0))) + fmaxf(v0, 0.f);
                o.y = log1pf(__expf(-fabsf(v1))) + fmaxf(v1, 0.f);
                o.z = log1pf(__expf(-fabsf(v2))) + fmaxf(v2, 0.f);
                o.w = log1pf(__expf(-fabsf(v3))) + fmaxf(v3, 0.f);
                *(float4*)&out[(size_t)node * KK + cg2 * 4] = o;
            }
        }
    }
}

// =====================================================================
extern "C" void kernel_launch(void* const* d_in, const int* in_sizes, int n_in,
                              void* d_out, int out_size) {
    const float* x      = (const float*)d_in[0];
    const int*   src    = (const int*)  d_in[1];
    const int*   dst    = (const int*)  d_in[2];
    const float* basew  = (const float*)d_in[3];
    const float* enc_w1 = (const float*)d_in[4];
    const float* enc_b1 = (const float*)d_in[5];
    const float* enc_w2 = (const float*)d_in[6];
    const float* enc_b2 = (const float*)d_in[7];
    const float* gw1    = (const float*)d_in[8];
    const float* gb1    = (const float*)d_in[9];
    const float* gw2    = (const float*)d_in[10];
    const float* gb2    = (const float*)d_in[11];
    const float* uw1    = (const float*)d_in[12];
    const float* ub1    = (const float*)d_in[13];
    const float* uw2    = (const float*)d_in[14];
    const float* ub2    = (const float*)d_in[15];
    const float* lng    = (const float*)d_in[16];
    const float* lnb    = (const float*)d_in[17];
    const float* rho    = (const float*)d_in[18];
    const float* tw     = (const float*)d_in[19];
    const float* tb     = (const float*)d_in[20];
    float* out = (float*)d_out;

    cudaFuncSetAttribute(k_update, cudaFuncAttributeMaxDynamicSharedMemorySize, DSM_BYTES);

    int nblocks = (NN + NB - 1) / NB;
    k_encoder<<<nblocks, 256>>>(x, enc_w1, enc_b1, enc_w2, enc_b2, gw1, gb1);
    k_w0<<<(EE + 255) / 256, 256>>>(src, dst, basew, rho);

    for (int l = 0; l < LL; l++) {
        k_edge<<<EE / 32, 256>>>(gw2, gb2);
        k_update<<<nblocks, 256, DSM_BYTES>>>(uw1 + l * HH * HH, ub1 + l * HH,
                                              uw2 + l * HH * HH, ub2 + l * HH,
                                              lng + l * HH, lnb + l * HH,
                                              gw1, gb1, tw, tb, out,
                                              l < LL - 1 ? 1 : 0);
    }
}